// round 17
// baseline (speedup 1.0000x reference)
#include <cuda_runtime.h>
#include <cstdint>

#define PNUM 128
#define MAXBATCH 8192

typedef unsigned long long u64;

// ---- packed f32x2 helpers (sm_103a), all 2-source forms (RF-bank rt=2) ----
__device__ __forceinline__ u64 pk_add(u64 a, u64 b) {
    u64 r;
    asm("add.rn.f32x2 %0, %1, %2;" : "=l"(r) : "l"(a), "l"(b));
    return r;
}
__device__ __forceinline__ u64 pk_sub(u64 a, u64 b) {   // a - b (FADD2 w/ neg mod)
    u64 r;
    asm("sub.rn.f32x2 %0, %1, %2;" : "=l"(r) : "l"(a), "l"(b));
    return r;
}
__device__ __forceinline__ u64 pk_fma_sq(u64 x, u64 acc) {   // acc += x*x
    u64 r;
    asm("fma.rn.f32x2 %0, %1, %1, %2;" : "=l"(r) : "l"(x), "l"(acc));
    return r;
}
__device__ __forceinline__ u64 pk_pack(float lo, float hi) {
    u64 r;
    asm("mov.b64 %0, {%1, %2};" : "=l"(r) : "f"(lo), "f"(hi));
    return r;
}
__device__ __forceinline__ void pk_unpack(u64 v, float& lo, float& hi) {
    asm("mov.b64 {%0, %1}, %2;" : "=f"(lo), "=f"(hi) : "l"(v));
}

#define KNEG1 0xBF800000BF800000ULL     // packed (-1.0f, -1.0f)

// ---- cp.async helpers (16B, writes smem directly: zero register cost) ----
__device__ __forceinline__ void cpa16(uint32_t dst, const void* src) {
    asm volatile("cp.async.ca.shared.global [%0], [%1], 16;" :: "r"(dst), "l"(src));
}
__device__ __forceinline__ void cpa_commit() {
    asm volatile("cp.async.commit_group;" ::: "memory");
}
__device__ __forceinline__ void cpa_wait_1() {
    asm volatile("cp.async.wait_group 1;" ::: "memory");
}
__device__ __forceinline__ void cpa_wait_0() {
    asm volatile("cp.async.wait_group 0;" ::: "memory");
}

// Pad-every-4 ring: padded index RP(a) = a + 2*(a>>2).
//  - lane base a0 = 4l -> RP(a0) = 6l; 16B-chunk index 3l mod 8 is a bijection
//    per 8-lane phase -> conflict-free LDS.128.
//  - a0 % 4 == 0 -> RP(a0+c) - RP(a0) = c + 2*(c>>2) = RPD(c): lane-uniform,
//    compile-time => every gt load is LDS [Rbase + imm].
//  - pairs (a, a+1) with a even never straddle a pad; RP(even) is even -> 16B
//    aligned.
#define RP(a)  ((a) + 2 * ((a) >> 2))
#define RPD(c) ((c) + 2 * ((c) >> 2))
#define RING_SIZE (RP(256) + 4)         // guard pair a=256,257 at RP(256)=384

// smoothL1(d) = 0.5*d^2 - 0.5*(m-1)^2,  m = max(|d|, 1)
// fma pipe: FADD2(d=p-g), FFMA2(Q+=d*d), FADD2(r=m-1), FFMA2(R+=r*r) (rt=2 each)
// alu pipe: 2x FMNMX m,|d|,1.0 (abs = free src modifier)
__device__ __forceinline__ void evalpair(u64 p, u64 g, u64& sQ, u64& sR) {
    u64 d = pk_sub(p, g);
    sQ = pk_fma_sq(d, sQ);
    float dx, dy;
    pk_unpack(d, dx, dy);
    float mx = fmaxf(fabsf(dx), 1.0f);
    float my = fmaxf(fabsf(dy), 1.0f);
    u64 m = pk_pack(mx, my);
    u64 r = pk_add(m, KNEG1);           // r = m - 1
    sR = pk_fma_sq(r, sR);
}

// One batch's matching pass: lane l handles shifts 4l..4l+3 of pred w.
// Returns min over this lane's 4 shifts (pre-shfl), scaled.
__device__ __forceinline__ float run_shifts(const u64* __restrict__ spw,
                                            const u64* __restrict__ rbase) {
    ulonglong2 C0 = *reinterpret_cast<const ulonglong2*>(&rbase[RPD(0)]);
    ulonglong2 C1 = *reinterpret_cast<const ulonglong2*>(&rbase[RPD(2)]);
    ulonglong2 C2 = *reinterpret_cast<const ulonglong2*>(&rbase[RPD(4)]);
    ulonglong2 C3;
    ulonglong2 P0 = *reinterpret_cast<const ulonglong2*>(&spw[0]);
    ulonglong2 P1;

    u64 Q0 = 0, R0 = 0, Q1 = 0, R1 = 0, Q2 = 0, R2 = 0, Q3 = 0, R3 = 0;

    // Step s covers i = 2s, 2s+1 for all 4 shifts; Pa was prefetched at s-1.
#define STEP(Ca, Cb, Cc, Cd, Pa, Pb, s)                                          \
    {                                                                            \
        Pb = *reinterpret_cast<const ulonglong2*>(&spw[2 * (s) + 2]);            \
        Cd = *reinterpret_cast<const ulonglong2*>(&rbase[RPD(2 * (s) + 6)]);     \
        evalpair(Pa.x, Ca.x, Q0, R0); evalpair(Pa.y, Ca.y, Q0, R0);              \
        evalpair(Pa.x, Ca.y, Q1, R1); evalpair(Pa.y, Cb.x, Q1, R1);              \
        evalpair(Pa.x, Cb.x, Q2, R2); evalpair(Pa.y, Cb.y, Q2, R2);              \
        evalpair(Pa.x, Cb.y, Q3, R3); evalpair(Pa.y, Cc.x, Q3, R3);              \
    }

#pragma unroll 4
    for (int su = 0; su < 16; su++) {
        const int s = 4 * su;
        STEP(C0, C1, C2, C3, P0, P1, s + 0)
        STEP(C1, C2, C3, C0, P1, P0, s + 1)
        STEP(C2, C3, C0, C1, P0, P1, s + 2)
        STEP(C3, C0, C1, C2, P1, P0, s + 3)
    }
#undef STEP

    float qx, qy, rx, ry;
    pk_unpack(Q0, qx, qy); pk_unpack(R0, rx, ry);
    float d0 = (qx + qy) - (rx + ry);
    pk_unpack(Q1, qx, qy); pk_unpack(R1, rx, ry);
    float d1 = (qx + qy) - (rx + ry);
    pk_unpack(Q2, qx, qy); pk_unpack(R2, rx, ry);
    float d2 = (qx + qy) - (rx + ry);
    pk_unpack(Q3, qx, qy); pk_unpack(R3, rx, ry);
    float d3 = (qx + qy) - (rx + ry);
    return fminf(fminf(d0, d1), fminf(d2, d3)) * (0.5f / PNUM);
}

__global__ __launch_bounds__(64)
void match_kernel(const float* __restrict__ pred0,
                  const float* __restrict__ pred1,
                  const float* __restrict__ gt,
                  float* __restrict__ out,
                  float scale,               // 0.5 / nbatch
                  int nbatch) {
    // Double-buffered: [buf][pred][point-pair]; +2 guard entries for the dead
    // final P-prefetch. ring holds RAW gt bytes (sub in evalpair).
    __shared__ __align__(16) u64 sp[2][2][PNUM + 2];
    __shared__ __align__(16) u64 ring[2][RING_SIZE];

    const int tid = threadIdx.x;        // 64 threads
    const int bA = 2 * blockIdx.x;
    const bool hasB = (bA + 1 < nbatch);
    const int fA = bA * 2 * PNUM;                       // float base, batch A
    const int fB = (hasB ? bA + 1 : bA) * 2 * PNUM;     // clamped if no B

    // Stage both batches via cp.async (no registers consumed). Group 0 = A,
    // group 1 = B; B's DRAM latency hides under A's wait + mainloop.
    {
        const int o16 = 4 * tid;        // 16B-aligned float offset per thread
        cpa16(__cvta_generic_to_shared(&sp[0][0][2 * tid]), pred0 + fA + o16);
        cpa16(__cvta_generic_to_shared(&sp[0][1][2 * tid]), pred1 + fA + o16);
        cpa16(__cvta_generic_to_shared(&ring[0][RP(2 * tid)]), gt + fA + o16);
        cpa16(__cvta_generic_to_shared(&ring[0][RP(2 * tid + 128)]), gt + fA + o16);
        if (tid == 0)
            cpa16(__cvta_generic_to_shared(&ring[0][RP(256)]), gt + fA);
        cpa_commit();   // group: A

        cpa16(__cvta_generic_to_shared(&sp[1][0][2 * tid]), pred0 + fB + o16);
        cpa16(__cvta_generic_to_shared(&sp[1][1][2 * tid]), pred1 + fB + o16);
        cpa16(__cvta_generic_to_shared(&ring[1][RP(2 * tid)]), gt + fB + o16);
        cpa16(__cvta_generic_to_shared(&ring[1][RP(2 * tid + 128)]), gt + fB + o16);
        if (tid == 0)
            cpa16(__cvta_generic_to_shared(&ring[1][RP(256)]), gt + fB);
        cpa_commit();   // group: B
    }

    const int l = tid & 31;
    const int w = tid >> 5;

    // ---- Batch A ----
    cpa_wait_1();       // A's group complete (B may still be in flight)
    __syncthreads();

    float disA = run_shifts(sp[0][w], &ring[0][6 * l]);
#pragma unroll
    for (int o = 16; o > 0; o >>= 1)
        disA = fminf(disA, __shfl_xor_sync(0xffffffffu, disA, o));
    if (l == 0)
        atomicAdd(out, disA * scale);   // fire-and-forget REDG

    // ---- Batch B ----
    cpa_wait_0();       // all groups complete
    __syncthreads();    // cross-thread visibility of B's copies

    if (hasB) {
        float disB = run_shifts(sp[1][w], &ring[1][6 * l]);
#pragma unroll
        for (int o = 16; o > 0; o >>= 1)
            disB = fminf(disB, __shfl_xor_sync(0xffffffffu, disB, o));
        if (l == 0)
            atomicAdd(out, disB * scale);
    }
}

extern "C" void kernel_launch(void* const* d_in, const int* in_sizes, int n_in,
                              void* d_out, int out_size) {
    const float* pred0 = (const float*)d_in[0];
    const float* pred1 = (const float*)d_in[1];
    const float* gt    = (const float*)d_in[2];
    int nbatch = in_sizes[0] / (PNUM * 2);
    if (nbatch > MAXBATCH) nbatch = MAXBATCH;
    int nblocks = (nbatch + 1) / 2;

    // d_out is poisoned 0xAA by the harness; zero it (graph memset node).
    cudaMemsetAsync(d_out, 0, sizeof(float));
    match_kernel<<<nblocks, 64>>>(pred0, pred1, gt, (float*)d_out,
                                  0.5f / (float)nbatch, nbatch);
}